// round 1
// baseline (speedup 1.0000x reference)
#include <cuda_runtime.h>

// ReduceBoundingBoxes: prob-threshold -> stable sort by score desc -> greedy NMS
// Input:  x (5, 80, 80) f32, channel-major: channel c at x[c*6400 + i]
// Output: (6400, 5) f32 row-major, row r = b5_sorted[r] if kept else 0
//
// Key facts exploited:
//  - only rows with prob > 0.9 can be nonzero in output (~10% of 6400)
//  - boxes with w<=0 or h<=0 have IoU 0 with everything -> excluded from NMS,
//    kept unconditionally (h = f4-f0-f2 with f0>0.9 is almost always <= 0)
//  - stable sort reproduced by rank-count with (score desc, idx asc) tie-break

#define NPIX 6400
#define NTHREADS 1024

// dynamic smem layout (bytes):
//   [0,      25600)  float sc[6400]      (valid scores, unsorted)   -- aliased later as int ndlist[6400]
//   [25600,  51200)  int   id[6400]      (valid indices, unsorted)
//   [51200,  76800)  int   sidx[6400]    (original index per sorted rank)
//   [76800, 204800)  float b5[5][6400]   (b5 columns per sorted rank)
//   [204800,211200)  uchar ndflag[6400]
//   [211200,217600)  uchar keepR[6400]
//   [217600,224000)  uchar kb[6400]      (keep bit per NMS-list entry)
#define SMEM_BYTES 224000

__global__ void __launch_bounds__(NTHREADS, 1)
reduce_bboxes_kernel(const float* __restrict__ x, float* __restrict__ out) {
    extern __shared__ unsigned char smem[];
    float* sc            = (float*)smem;
    int*   ndlist        = (int*)smem;              // alias of sc (used after sort)
    int*   id            = (int*)(smem + 25600);
    int*   sidx          = (int*)(smem + 51200);
    float* b5            = (float*)(smem + 76800);  // stride NPIX per column
    unsigned char* ndflag = smem + 204800;
    unsigned char* keepR  = smem + 211200;
    unsigned char* kb     = smem + 217600;

    __shared__ int cntV;
    const int tid = threadIdx.x;

    // ---- phase 0: zero the output (d_out is poisoned) ----
    float4* o4 = (float4*)out;
    for (int i = tid; i < (NPIX * 5) / 4; i += NTHREADS)
        o4[i] = make_float4(0.f, 0.f, 0.f, 0.f);

    if (tid == 0) cntV = 0;
    __syncthreads();

    // ---- phase 1: compact valid rows (prob > 0.9) ----
    for (int i = tid; i < NPIX; i += NTHREADS) {
        float s = x[i];  // channel 0
        if (s > 0.9f) {
            int p = atomicAdd(&cntV, 1);
            sc[p] = s;
            id[p] = i;
        }
    }
    __syncthreads();
    const int M = cntV;

    // ---- phase 2: stable rank sort (score desc, index asc) ----
    for (int k = tid; k < M; k += NTHREADS) {
        float sk = sc[k];
        int   ik = id[k];
        int   r  = 0;
        for (int j = 0; j < M; j++) {
            float sj = sc[j];
            if (sj > sk)                      r++;
            else if (sj == sk && id[j] < ik)  r++;
        }
        sidx[r] = ik;  // ranks are distinct (indices distinct)
    }
    __syncthreads();

    // ---- phase 3: build b5 per rank, degeneracy flag, keep init ----
    for (int r = tid; r < M; r += NTHREADS) {
        int i = sidx[r];
        float f0 = x[i];
        float f1 = x[NPIX + i];
        float f2 = x[2 * NPIX + i];
        float f3 = x[3 * NPIX + i];
        float f4 = x[4 * NPIX + i];
        float c2 = f0 + f2;
        float c3 = f1 + f3;
        b5[0 * NPIX + r] = f0;
        b5[1 * NPIX + r] = f1;
        b5[2 * NPIX + r] = c2;
        b5[3 * NPIX + r] = c3;
        b5[4 * NPIX + r] = f4;
        // box = (x0,y0,x1,y1) = (f1, c2, c3, f4); w = c3-f1 = f3, h = f4-c2
        float w = c3 - f1;
        float h = f4 - c2;
        ndflag[r] = (w > 0.f && h > 0.f) ? 1 : 0;
        keepR[r]  = 1;  // degenerate valid boxes are always kept
    }
    __syncthreads();

    // ---- phase 4: warp 0 — greedy NMS over non-degenerate boxes only ----
    if (tid < 32) {
        const int lane = tid;
        // compact non-degenerate ranks (rank order preserved) via ballot scan
        int g = 0;
        for (int base = 0; base < M; base += 32) {
            int r = base + lane;
            bool f = (r < M) && (ndflag[r] != 0);
            unsigned bal = __ballot_sync(0xffffffffu, f);
            if (f) ndlist[g + __popc(bal & ((1u << lane) - 1u))] = r;
            g += __popc(bal);
        }
        // greedy sequential NMS (g is tiny in practice; warp-parallel inner loop)
        for (int i2 = 0; i2 < g; i2++) {
            int ri = ndlist[i2];
            float ax0 = b5[1 * NPIX + ri], ay0 = b5[2 * NPIX + ri];
            float ax1 = b5[3 * NPIX + ri], ay1 = b5[4 * NPIX + ri];
            float aarea = fmaxf(ax1 - ax0, 0.f) * fmaxf(ay1 - ay0, 0.f);
            bool sup = false;
            for (int j = lane; j < i2; j += 32) {
                if (kb[j]) {
                    int rj = ndlist[j];
                    float bx0 = b5[1 * NPIX + rj], by0 = b5[2 * NPIX + rj];
                    float bx1 = b5[3 * NPIX + rj], by1 = b5[4 * NPIX + rj];
                    float barea = fmaxf(bx1 - bx0, 0.f) * fmaxf(by1 - by0, 0.f);
                    float iw = fminf(ax1, bx1) - fmaxf(ax0, bx0);
                    float ih = fminf(ay1, by1) - fmaxf(ay0, by0);
                    float inter = fmaxf(iw, 0.f) * fmaxf(ih, 0.f);
                    float uni = aarea + barea - inter;
                    float iou = inter / fmaxf(uni, 1e-9f);
                    if (iou > 0.5f) sup = true;
                }
            }
            sup = __any_sync(0xffffffffu, sup);
            if (lane == 0) {
                kb[i2] = sup ? 0 : 1;
                if (sup) keepR[ri] = 0;
            }
            __syncwarp();
        }
    }
    __syncthreads();

    // ---- phase 5: scatter kept rows (zeros already written) ----
    for (int r = tid; r < M; r += NTHREADS) {
        if (keepR[r]) {
            out[r * 5 + 0] = b5[0 * NPIX + r];
            out[r * 5 + 1] = b5[1 * NPIX + r];
            out[r * 5 + 2] = b5[2 * NPIX + r];
            out[r * 5 + 3] = b5[3 * NPIX + r];
            out[r * 5 + 4] = b5[4 * NPIX + r];
        }
    }
}

extern "C" void kernel_launch(void* const* d_in, const int* in_sizes, int n_in,
                              void* d_out, int out_size) {
    const float* x = (const float*)d_in[0];
    float* out = (float*)d_out;
    cudaFuncSetAttribute(reduce_bboxes_kernel,
                         cudaFuncAttributeMaxDynamicSharedMemorySize, SMEM_BYTES);
    reduce_bboxes_kernel<<<1, NTHREADS, SMEM_BYTES>>>(x, out);
}

// round 2
// speedup vs baseline: 2.6193x; 2.6193x over previous
#include <cuda_runtime.h>

// ReduceBoundingBoxes: prob-threshold -> stable sort by score desc -> greedy NMS
// x: (5, 80, 80) f32 channel-major. out: (6400, 5) f32.
// Two kernels:
//   A (grid-wide): zero out, compact valid (prob>0.9) into global scratch.
//   B (1 block):   bitonic-sort packed keys, write sorted rows, tiny NMS.

#define NPIX 6400
#define NT_B 1024

__device__ float d_sc[NPIX];
__device__ int   d_idv[NPIX];
__device__ int   d_cnt;   // zero-init; kernel B resets it at the end of each run

__global__ void bb_compact_kernel(const float* __restrict__ x,
                                  float* __restrict__ out) {
    int tid  = blockIdx.x * blockDim.x + threadIdx.x;
    int nthr = gridDim.x * blockDim.x;
    // zero output (6400*5 floats = 8000 float4)
    float4* o4 = (float4*)out;
    for (int i = tid; i < (NPIX * 5) / 4; i += nthr)
        o4[i] = make_float4(0.f, 0.f, 0.f, 0.f);
    // compact valid rows
    for (int i = tid; i < NPIX; i += nthr) {
        float s = x[i];                 // channel 0 (prob)
        if (s > 0.9f) {
            int p = atomicAdd(&d_cnt, 1);
            d_sc[p]  = s;
            d_idv[p] = i;
        }
    }
}

// dynamic smem: keys u64[8192] = 65536 B | ndflag u8[6400] | kb u8[6400]
#define SMEM_B (65536 + NPIX + NPIX)

__global__ void __launch_bounds__(NT_B, 1)
bb_sort_nms_kernel(const float* __restrict__ x, float* __restrict__ out) {
    extern __shared__ unsigned char smem[];
    unsigned long long* keys  = (unsigned long long*)smem;
    unsigned char*      ndflag = smem + 65536;
    unsigned char*      kb     = smem + 65536 + NPIX;
    int*                ndlist = (int*)smem;   // alias keys; used only after
                                               // keys are dead (post phase 3)
    const int tid = threadIdx.x;
    const int M = d_cnt;

    if (M > 0) {
        // next pow2 >= M
        int n = 1;
        while (n < M) n <<= 1;

        // build keys: ascending u64 order == (score desc, idx asc).
        // scores are positive floats -> bit pattern is order-preserving.
        for (int k = tid; k < n; k += NT_B) {
            if (k < M) {
                unsigned b = __float_as_uint(d_sc[k]);
                keys[k] = (((unsigned long long)(~b)) << 32) |
                          (unsigned)d_idv[k];
            } else {
                keys[k] = 0xFFFFFFFFFFFFFFFFull;  // padding sinks to the end
            }
        }
        __syncthreads();

        // in-smem bitonic sort, ascending
        for (int kk = 2; kk <= n; kk <<= 1) {
            for (int j = kk >> 1; j > 0; j >>= 1) {
                for (int i = tid; i < n; i += NT_B) {
                    int ixj = i ^ j;
                    if (ixj > i) {
                        unsigned long long a = keys[i];
                        unsigned long long c = keys[ixj];
                        bool asc = ((i & kk) == 0);
                        if ((a > c) == asc) { keys[i] = c; keys[ixj] = a; }
                    }
                }
                __syncthreads();
            }
        }

        // phase 3: gather channels by sorted original index, write rows,
        // flag non-degenerate boxes. box = (f1, f0+f2, f1+f3, f4);
        // w = f3, h = f4 - (f0+f2).
        for (int r = tid; r < M; r += NT_B) {
            int i = (int)(unsigned)(keys[r] & 0xffffffffull);
            float f0 = x[i];
            float f1 = x[NPIX + i];
            float f2 = x[2 * NPIX + i];
            float f3 = x[3 * NPIX + i];
            float f4 = x[4 * NPIX + i];
            float c2 = f0 + f2;
            float c3 = f1 + f3;
            out[r * 5 + 0] = f0;
            out[r * 5 + 1] = f1;
            out[r * 5 + 2] = c2;
            out[r * 5 + 3] = c3;
            out[r * 5 + 4] = f4;
            ndflag[r] = ((c3 - f1) > 0.f && (f4 - c2) > 0.f) ? 1 : 0;
        }
        __syncthreads();   // also makes global `out` writes block-visible

        // phase 4: warp 0 — greedy NMS over non-degenerate boxes only.
        // Degenerate boxes have IoU 0 with everything: never suppressed,
        // never suppress -> their rows stay as written.
        if (tid < 32) {
            const int lane = tid;
            int g = 0;
            for (int base = 0; base < M; base += 32) {
                int r = base + lane;
                bool f = (r < M) && (ndflag[r] != 0);
                unsigned bal = __ballot_sync(0xffffffffu, f);
                if (f) ndlist[g + __popc(bal & ((1u << lane) - 1u))] = r;
                g += __popc(bal);
            }
            for (int i2 = 0; i2 < g; i2++) {
                int ri = ndlist[i2];
                float ax0 = out[ri * 5 + 1], ay0 = out[ri * 5 + 2];
                float ax1 = out[ri * 5 + 3], ay1 = out[ri * 5 + 4];
                float aarea = fmaxf(ax1 - ax0, 0.f) * fmaxf(ay1 - ay0, 0.f);
                bool sup = false;
                for (int j = lane; j < i2; j += 32) {
                    if (kb[j]) {
                        int rj = ndlist[j];
                        float bx0 = out[rj * 5 + 1], by0 = out[rj * 5 + 2];
                        float bx1 = out[rj * 5 + 3], by1 = out[rj * 5 + 4];
                        float barea = fmaxf(bx1 - bx0, 0.f) *
                                      fmaxf(by1 - by0, 0.f);
                        float iw = fminf(ax1, bx1) - fmaxf(ax0, bx0);
                        float ih = fminf(ay1, by1) - fmaxf(ay0, by0);
                        float inter = fmaxf(iw, 0.f) * fmaxf(ih, 0.f);
                        float uni = aarea + barea - inter;
                        if (inter / fmaxf(uni, 1e-9f) > 0.5f) sup = true;
                    }
                }
                sup = __any_sync(0xffffffffu, sup);
                if (lane == 0) {
                    kb[i2] = sup ? 0 : 1;
                    if (sup) {   // suppressed row -> zeros
                        out[ri * 5 + 0] = 0.f;
                        out[ri * 5 + 1] = 0.f;
                        out[ri * 5 + 2] = 0.f;
                        out[ri * 5 + 3] = 0.f;
                        out[ri * 5 + 4] = 0.f;
                    }
                }
                __syncwarp();
            }
        }
    }

    __syncthreads();
    if (tid == 0) d_cnt = 0;   // reset for the next graph replay
}

extern "C" void kernel_launch(void* const* d_in, const int* in_sizes, int n_in,
                              void* d_out, int out_size) {
    const float* x = (const float*)d_in[0];
    float* out = (float*)d_out;
    cudaFuncSetAttribute(bb_sort_nms_kernel,
                         cudaFuncAttributeMaxDynamicSharedMemorySize, SMEM_B);
    bb_compact_kernel<<<64, 256>>>(x, out);
    bb_sort_nms_kernel<<<1, NT_B, SMEM_B>>>(x, out);
}

// round 3
// speedup vs baseline: 3.2411x; 1.2374x over previous
#include <cuda_runtime.h>

// ReduceBoundingBoxes, single-kernel: zero out -> threshold-compact into smem
// packed keys -> hybrid shfl/smem bitonic sort -> gather+write rows -> tiny NMS.
// x: (5, 80, 80) f32 channel-major. out: (6400, 5) f32.

#define NPIX 6400
#define NT 1024

// dynamic smem layout (bytes):
//   [0,      65536)  u64 keys[8192]     (worst-case M=6400 -> n=8192)
//                    aliased as int ndlist[] after keys are dead
//   [65536, 167936)  float4 bx[6400]    (x0,y0,x1,y1 per sorted rank)
//   [167936,174336)  u8 ndflag[6400]
//   [174336,180736)  u8 kb[6400]
#define KEYS_OFF   0
#define BOX_OFF    65536
#define NDFLAG_OFF 167936
#define KB_OFF     174336
#define SMEM_BYTES 180736

__global__ void __launch_bounds__(NT, 1)
bb_kernel(const float* __restrict__ x, float* __restrict__ out) {
    extern __shared__ unsigned char smem[];
    unsigned long long* keys   = (unsigned long long*)(smem + KEYS_OFF);
    float4*             bx     = (float4*)(smem + BOX_OFF);
    unsigned char*      ndflag = smem + NDFLAG_OFF;
    unsigned char*      kb     = smem + KB_OFF;
    int*                ndlist = (int*)(smem + KEYS_OFF);  // alias, post-sort
    __shared__ int cnt;
    const int tid = threadIdx.x;

    // ---- zero output (6400*5 f32 = 8000 float4) ----
    float4* o4 = (float4*)out;
    #pragma unroll
    for (int i = tid; i < (NPIX * 5) / 4; i += NT)
        o4[i] = make_float4(0.f, 0.f, 0.f, 0.f);

    if (tid == 0) cnt = 0;
    __syncthreads();

    // ---- compact valid rows (prob > 0.9) into packed keys ----
    // ascending u64 order == (score desc, idx asc); scores positive floats.
    for (int i = tid; i < NPIX; i += NT) {
        float s = x[i];  // channel 0
        if (s > 0.9f) {
            int p = atomicAdd(&cnt, 1);
            keys[p] = (((unsigned long long)(~__float_as_uint(s))) << 32) |
                      (unsigned)i;
        }
    }
    __syncthreads();
    const int M = cnt;

    if (M > 0) {
        if (M <= NT) {
            // ---- fast path: fixed n=1024, 1 elt/thread hybrid bitonic ----
            if (tid >= M) keys[tid] = ~0ull;  // pad sinks to the end
            __syncthreads();
            unsigned long long v = keys[tid];

            // kk = 2..32: fully intra-warp (registers + shfl, no barriers)
            #pragma unroll
            for (int kk = 2; kk <= 32; kk <<= 1) {
                #pragma unroll
                for (int j = kk >> 1; j >= 1; j >>= 1) {
                    unsigned long long o = __shfl_xor_sync(0xffffffffu, v, j);
                    bool keepmin = (((tid & kk) == 0) == ((tid & j) == 0));
                    v = keepmin ? (v < o ? v : o) : (v > o ? v : o);
                }
            }
            keys[tid] = v;
            __syncthreads();

            // kk = 64..1024: smem steps for j>=32, then shfl for j<=16
            #pragma unroll
            for (int kk = 64; kk <= 1024; kk <<= 1) {
                for (int j = kk >> 1; j >= 32; j >>= 1) {
                    int ixj = tid ^ j;
                    if (ixj > tid) {
                        unsigned long long a = keys[tid];
                        unsigned long long c = keys[ixj];
                        bool asc = ((tid & kk) == 0);
                        if ((a > c) == asc) { keys[tid] = c; keys[ixj] = a; }
                    }
                    __syncthreads();
                }
                v = keys[tid];
                #pragma unroll
                for (int j = 16; j >= 1; j >>= 1) {
                    unsigned long long o = __shfl_xor_sync(0xffffffffu, v, j);
                    bool keepmin = (((tid & kk) == 0) == ((tid & j) == 0));
                    v = keepmin ? (v < o ? v : o) : (v > o ? v : o);
                }
                keys[tid] = v;
                __syncthreads();
            }
        } else {
            // ---- generic fallback: smem bitonic up to n=8192 ----
            int n = 1;
            while (n < M) n <<= 1;
            for (int k = M + tid; k < n; k += NT) keys[k] = ~0ull;
            __syncthreads();
            for (int kk = 2; kk <= n; kk <<= 1) {
                for (int j = kk >> 1; j > 0; j >>= 1) {
                    for (int i = tid; i < n; i += NT) {
                        int ixj = i ^ j;
                        if (ixj > i) {
                            unsigned long long a = keys[i];
                            unsigned long long c = keys[ixj];
                            bool asc = ((i & kk) == 0);
                            if ((a > c) == asc) { keys[i] = c; keys[ixj] = a; }
                        }
                    }
                    __syncthreads();
                }
            }
        }

        // ---- gather channels by sorted index, write rows, stage boxes ----
        // box = (x0,y0,x1,y1) = (f1, f0+f2, f1+f3, f4); w=f3, h=f4-(f0+f2)
        for (int r = tid; r < M; r += NT) {
            int i = (int)(unsigned)(keys[r] & 0xffffffffull);
            float f0 = x[i];
            float f1 = x[NPIX + i];
            float f2 = x[2 * NPIX + i];
            float f3 = x[3 * NPIX + i];
            float f4 = x[4 * NPIX + i];
            float c2 = f0 + f2;
            float c3 = f1 + f3;
            out[r * 5 + 0] = f0;
            out[r * 5 + 1] = f1;
            out[r * 5 + 2] = c2;
            out[r * 5 + 3] = c3;
            out[r * 5 + 4] = f4;
            bx[r] = make_float4(f1, c2, c3, f4);
            ndflag[r] = ((c3 - f1) > 0.f && (f4 - c2) > 0.f) ? 1 : 0;
        }
        __syncthreads();

        // ---- warp 0: greedy NMS over non-degenerate boxes only ----
        // degenerate boxes (w<=0 or h<=0) have IoU 0 with everything:
        // never suppressed, never suppress -> rows stay as written.
        if (tid < 32) {
            const int lane = tid;
            int g = 0;
            for (int base = 0; base < M; base += 32) {
                int r = base + lane;
                bool f = (r < M) && (ndflag[r] != 0);
                unsigned bal = __ballot_sync(0xffffffffu, f);
                if (f) ndlist[g + __popc(bal & ((1u << lane) - 1u))] = r;
                g += __popc(bal);
            }
            for (int i2 = 0; i2 < g; i2++) {
                int ri = ndlist[i2];
                float4 a = bx[ri];
                float aarea = fmaxf(a.z - a.x, 0.f) * fmaxf(a.w - a.y, 0.f);
                bool sup = false;
                for (int j = lane; j < i2; j += 32) {
                    if (kb[j]) {
                        float4 b = bx[ndlist[j]];
                        float barea = fmaxf(b.z - b.x, 0.f) *
                                      fmaxf(b.w - b.y, 0.f);
                        float iw = fminf(a.z, b.z) - fmaxf(a.x, b.x);
                        float ih = fminf(a.w, b.w) - fmaxf(a.y, b.y);
                        float inter = fmaxf(iw, 0.f) * fmaxf(ih, 0.f);
                        float uni = aarea + barea - inter;
                        if (inter / fmaxf(uni, 1e-9f) > 0.5f) sup = true;
                    }
                }
                sup = __any_sync(0xffffffffu, sup);
                if (lane == 0) {
                    kb[i2] = sup ? 0 : 1;
                    if (sup) {  // suppressed row -> zeros
                        out[ri * 5 + 0] = 0.f;
                        out[ri * 5 + 1] = 0.f;
                        out[ri * 5 + 2] = 0.f;
                        out[ri * 5 + 3] = 0.f;
                        out[ri * 5 + 4] = 0.f;
                    }
                }
                __syncwarp();
            }
        }
    }
}

extern "C" void kernel_launch(void* const* d_in, const int* in_sizes, int n_in,
                              void* d_out, int out_size) {
    const float* x = (const float*)d_in[0];
    float* out = (float*)d_out;
    cudaFuncSetAttribute(bb_kernel,
                         cudaFuncAttributeMaxDynamicSharedMemorySize,
                         SMEM_BYTES);
    bb_kernel<<<1, NT, SMEM_BYTES>>>(x, out);
}

// round 4
// speedup vs baseline: 3.2903x; 1.0152x over previous
#include <cuda_runtime.h>

// ReduceBoundingBoxes, single-kernel:
//   zero out | prefetch channels 1..4 to smem | warp-aggregated threshold
//   compaction into packed keys | hybrid shfl/smem bitonic sort | gather from
//   smem (f0 recovered from key) | tiny NMS on non-degenerate boxes.
// x: (5, 80, 80) f32 channel-major. out: (6400, 5) f32.

#define NPIX 6400
#define NT 1024

// dynamic smem layout (bytes):
//   [0,      102400)  float xs[4*6400]   channels 1..4 (linear copy of
//                                        x[6400..32000))
//   [102400, 167936)  u64 keys[8192]     sort keys (fast path uses [0,1024);
//                                        [1024..) aliased as int ndlist[])
//   [167936, 174336)  u8 ndflag[6400]
//   [174336, 180736)  u8 kb[6400]
#define XS_OFF     0
#define KEYS_OFF   102400
#define NDLIST_OFF (KEYS_OFF + 8192)
#define NDFLAG_OFF 167936
#define KB_OFF     174336
#define SMEM_BYTES 180736

__device__ __forceinline__ float4 box_of(const float* xs, unsigned i,
                                         unsigned long long key) {
    float f0 = __uint_as_float(~(unsigned)(key >> 32));
    float f1 = xs[i];
    float f2 = xs[NPIX + i];
    float f3 = xs[2 * NPIX + i];
    float f4 = xs[3 * NPIX + i];
    return make_float4(f1, f0 + f2, f1 + f3, f4);
}

__global__ void __launch_bounds__(NT, 1)
bb_kernel(const float* __restrict__ x, float* __restrict__ out) {
    extern __shared__ unsigned char smem[];
    float*              xs     = (float*)(smem + XS_OFF);
    unsigned long long* keys   = (unsigned long long*)(smem + KEYS_OFF);
    int*                ndlist = (int*)(smem + NDLIST_OFF);  // fast path only
    unsigned char*      ndflag = smem + NDFLAG_OFF;
    unsigned char*      kb     = smem + KB_OFF;
    __shared__ int cnt;
    const int tid  = threadIdx.x;
    const int lane = tid & 31;

    // ---- zero output (8000 float4), fire-and-forget ----
    float4* o4 = (float4*)out;
    for (int i = tid; i < (NPIX * 5) / 4; i += NT)
        o4[i] = make_float4(0.f, 0.f, 0.f, 0.f);

    // ---- prefetch channels 1..4 into smem (6400 float4, linear) ----
    const float4* x14 = (const float4*)(x + NPIX);
    float4* xs4 = (float4*)xs;
    for (int i = tid; i < NPIX; i += NT)   // 4*6400 floats / 4 = 6400 float4
        xs4[i] = x14[i];

    if (tid == 0) cnt = 0;
    __syncthreads();

    // ---- warp-aggregated compaction of valid rows (prob > 0.9) ----
    // ascending u64 key order == (score desc, idx asc); scores positive.
    for (int i = tid; i < NPIX; i += NT) {
        float s = x[i];  // channel 0
        bool v = s > 0.9f;
        unsigned bal = __ballot_sync(0xffffffffu, v);
        if (bal) {
            int leader = __ffs(bal) - 1;
            int base;
            if (lane == leader) base = atomicAdd(&cnt, __popc(bal));
            base = __shfl_sync(0xffffffffu, base, leader);
            if (v) {
                int p = base + __popc(bal & ((1u << lane) - 1u));
                keys[p] = (((unsigned long long)(~__float_as_uint(s))) << 32)
                          | (unsigned)i;
            }
        }
    }
    __syncthreads();
    const int M = cnt;

    if (M > 0) {
        bool fast = (M <= NT);
        if (fast) {
            // ---- fixed n=1024, 1 elt/thread hybrid bitonic ----
            if (tid >= M) keys[tid] = ~0ull;
            __syncthreads();
            unsigned long long v = keys[tid];

            #pragma unroll
            for (int kk = 2; kk <= 32; kk <<= 1) {
                #pragma unroll
                for (int j = kk >> 1; j >= 1; j >>= 1) {
                    unsigned long long o = __shfl_xor_sync(0xffffffffu, v, j);
                    bool keepmin = (((tid & kk) == 0) == ((tid & j) == 0));
                    v = keepmin ? (v < o ? v : o) : (v > o ? v : o);
                }
            }
            keys[tid] = v;
            __syncthreads();

            #pragma unroll
            for (int kk = 64; kk <= 1024; kk <<= 1) {
                for (int j = kk >> 1; j >= 32; j >>= 1) {
                    int ixj = tid ^ j;
                    if (ixj > tid) {
                        unsigned long long a = keys[tid];
                        unsigned long long c = keys[ixj];
                        bool asc = ((tid & kk) == 0);
                        if ((a > c) == asc) { keys[tid] = c; keys[ixj] = a; }
                    }
                    __syncthreads();
                }
                v = keys[tid];
                #pragma unroll
                for (int j = 16; j >= 1; j >>= 1) {
                    unsigned long long o = __shfl_xor_sync(0xffffffffu, v, j);
                    bool keepmin = (((tid & kk) == 0) == ((tid & j) == 0));
                    v = keepmin ? (v < o ? v : o) : (v > o ? v : o);
                }
                keys[tid] = v;
                __syncthreads();
            }
        } else {
            // ---- generic smem bitonic fallback (M > 1024; ~never) ----
            int n = 1;
            while (n < M) n <<= 1;
            for (int k = M + tid; k < n; k += NT) keys[k] = ~0ull;
            __syncthreads();
            for (int kk = 2; kk <= n; kk <<= 1) {
                for (int j = kk >> 1; j > 0; j >>= 1) {
                    for (int i = tid; i < n; i += NT) {
                        int ixj = i ^ j;
                        if (ixj > i) {
                            unsigned long long a = keys[i];
                            unsigned long long c = keys[ixj];
                            bool asc = ((i & kk) == 0);
                            if ((a > c) == asc) { keys[i] = c; keys[ixj] = a; }
                        }
                    }
                    __syncthreads();
                }
            }
        }

        // ---- gather: write sorted rows from smem, flag non-degenerate ----
        // b5 = (f0, f1, f0+f2, f1+f3, f4); w = f3, h = f4 - (f0+f2)
        for (int r = tid; r < M; r += NT) {
            unsigned long long key = keys[r];
            unsigned i = (unsigned)key;
            float f0 = __uint_as_float(~(unsigned)(key >> 32));
            float f1 = xs[i];
            float f2 = xs[NPIX + i];
            float f3 = xs[2 * NPIX + i];
            float f4 = xs[3 * NPIX + i];
            float c2 = f0 + f2;
            float c3 = f1 + f3;
            out[r * 5 + 0] = f0;
            out[r * 5 + 1] = f1;
            out[r * 5 + 2] = c2;
            out[r * 5 + 3] = c3;
            out[r * 5 + 4] = f4;
            ndflag[r] = ((c3 - f1) > 0.f && (f4 - c2) > 0.f) ? 1 : 0;
        }
        __syncthreads();

        // ---- warp 0: greedy NMS over non-degenerate boxes only ----
        // degenerate boxes (w<=0 or h<=0) have IoU 0 with everything:
        // never suppressed, never suppress.
        if (tid < 32) {
            int g = 0;
            if (fast) {
                // compact non-degenerate ranks into ndlist (order preserved)
                for (int base = 0; base < M; base += 32) {
                    int r = base + lane;
                    bool f = (r < M) && (ndflag[r] != 0);
                    unsigned bal = __ballot_sync(0xffffffffu, f);
                    if (f) ndlist[g + __popc(bal & ((1u << lane) - 1u))] = r;
                    g += __popc(bal);
                }
                for (int i2 = 0; i2 < g; i2++) {
                    int ri = ndlist[i2];
                    float4 a = box_of(xs, (unsigned)keys[ri], keys[ri]);
                    float aarea = fmaxf(a.z - a.x, 0.f) * fmaxf(a.w - a.y, 0.f);
                    bool sup = false;
                    for (int j = lane; j < i2; j += 32) {
                        if (kb[j]) {
                            int rj = ndlist[j];
                            float4 b = box_of(xs, (unsigned)keys[rj], keys[rj]);
                            float barea = fmaxf(b.z - b.x, 0.f) *
                                          fmaxf(b.w - b.y, 0.f);
                            float iw = fminf(a.z, b.z) - fmaxf(a.x, b.x);
                            float ih = fminf(a.w, b.w) - fmaxf(a.y, b.y);
                            float inter = fmaxf(iw, 0.f) * fmaxf(ih, 0.f);
                            float uni = aarea + barea - inter;
                            if (inter / fmaxf(uni, 1e-9f) > 0.5f) sup = true;
                        }
                    }
                    sup = __any_sync(0xffffffffu, sup);
                    if (lane == 0) {
                        kb[i2] = sup ? 0 : 1;
                        if (sup) {
                            out[ri * 5 + 0] = 0.f;
                            out[ri * 5 + 1] = 0.f;
                            out[ri * 5 + 2] = 0.f;
                            out[ri * 5 + 3] = 0.f;
                            out[ri * 5 + 4] = 0.f;
                        }
                    }
                    __syncwarp();
                }
            } else {
                // fallback (M > 1024): no ndlist space — direct serial scan.
                // kb[r] indexed by rank here.
                for (int r = 0; r < M; r++) {
                    if (lane == 0) kb[r] = 0;
                    __syncwarp();
                    if (!ndflag[r]) continue;
                    float4 a = box_of(xs, (unsigned)keys[r], keys[r]);
                    float aarea = fmaxf(a.z - a.x, 0.f) * fmaxf(a.w - a.y, 0.f);
                    bool sup = false;
                    for (int j = lane; j < r; j += 32) {
                        if (kb[j]) {
                            float4 b = box_of(xs, (unsigned)keys[j], keys[j]);
                            float barea = fmaxf(b.z - b.x, 0.f) *
                                          fmaxf(b.w - b.y, 0.f);
                            float iw = fminf(a.z, b.z) - fmaxf(a.x, b.x);
                            float ih = fminf(a.w, b.w) - fmaxf(a.y, b.y);
                            float inter = fmaxf(iw, 0.f) * fmaxf(ih, 0.f);
                            float uni = aarea + barea - inter;
                            if (inter / fmaxf(uni, 1e-9f) > 0.5f) sup = true;
                        }
                    }
                    sup = __any_sync(0xffffffffu, sup);
                    if (lane == 0) {
                        kb[r] = sup ? 0 : 1;
                        if (sup) {
                            out[r * 5 + 0] = 0.f;
                            out[r * 5 + 1] = 0.f;
                            out[r * 5 + 2] = 0.f;
                            out[r * 5 + 3] = 0.f;
                            out[r * 5 + 4] = 0.f;
                        }
                    }
                    __syncwarp();
                }
            }
        }
    }
}

extern "C" void kernel_launch(void* const* d_in, const int* in_sizes, int n_in,
                              void* d_out, int out_size) {
    const float* x = (const float*)d_in[0];
    float* out = (float*)d_out;
    cudaFuncSetAttribute(bb_kernel,
                         cudaFuncAttributeMaxDynamicSharedMemorySize,
                         SMEM_BYTES);
    bb_kernel<<<1, NT, SMEM_BYTES>>>(x, out);
}

// round 5
// speedup vs baseline: 3.3282x; 1.0115x over previous
#include <cuda_runtime.h>

// ReduceBoundingBoxes, 3-kernel pipeline:
//   K1 (grid-wide): zero out + warp-aggregated threshold compaction -> d_keys
//   K2 (1 block):   hybrid shfl/smem bitonic sort of packed keys
//   K3 (1 block):   gather + write sorted rows + tiny NMS (+ reset counter)
// x: (5, 80, 80) f32 channel-major. out: (6400, 5) f32.
// key = (~bits(score) << 32) | idx  -> ascending u64 == (score desc, idx asc)

#define NPIX 6400
#define NT 1024

__device__ unsigned long long d_keys[NPIX];
__device__ int d_cnt;   // zero-init; K3 resets it each run

// ---------------- K1: zero output + compact valid rows ----------------
__global__ void __launch_bounds__(256)
bb_compact(const float* __restrict__ x, float* __restrict__ out) {
    int gtid = blockIdx.x * 256 + threadIdx.x;   // grid 64x256 = 16384
    // zero output: 6400*5 f32 = 8000 float4
    if (gtid < (NPIX * 5) / 4)
        ((float4*)out)[gtid] = make_float4(0.f, 0.f, 0.f, 0.f);
    // compaction: one pixel per thread (6400 = 200 full warps)
    if (gtid < NPIX) {
        float s = x[gtid];                        // channel 0 (prob)
        bool v = s > 0.9f;
        unsigned bal = __ballot_sync(0xffffffffu, v);
        if (bal) {
            int lane = threadIdx.x & 31;
            int leader = __ffs(bal) - 1;
            int base;
            if (lane == leader) base = atomicAdd(&d_cnt, __popc(bal));
            base = __shfl_sync(0xffffffffu, base, leader);
            if (v) {
                int p = base + __popc(bal & ((1u << lane) - 1u));
                d_keys[p] =
                    (((unsigned long long)(~__float_as_uint(s))) << 32) |
                    (unsigned)gtid;
            }
        }
    }
}

// ---------------- K2: sort keys ----------------
#define SMEM_SORT 65536   // u64 skeys[8192]

__global__ void __launch_bounds__(NT, 1)
bb_sort() {
    extern __shared__ unsigned long long skeys[];
    const int tid = threadIdx.x;
    const int M = d_cnt;
    if (M <= 1) return;   // 0 or 1 element: already sorted

    if (M <= NT) {
        // fast path: fixed n=1024, 1 elt/thread
        unsigned long long v = (tid < M) ? d_keys[tid] : ~0ull;

        #pragma unroll
        for (int kk = 2; kk <= 32; kk <<= 1) {
            #pragma unroll
            for (int j = kk >> 1; j >= 1; j >>= 1) {
                unsigned long long o = __shfl_xor_sync(0xffffffffu, v, j);
                bool keepmin = (((tid & kk) == 0) == ((tid & j) == 0));
                v = keepmin ? (v < o ? v : o) : (v > o ? v : o);
            }
        }
        skeys[tid] = v;
        __syncthreads();

        #pragma unroll
        for (int kk = 64; kk <= 1024; kk <<= 1) {
            for (int j = kk >> 1; j >= 32; j >>= 1) {
                int ixj = tid ^ j;
                if (ixj > tid) {
                    unsigned long long a = skeys[tid];
                    unsigned long long c = skeys[ixj];
                    bool asc = ((tid & kk) == 0);
                    if ((a > c) == asc) { skeys[tid] = c; skeys[ixj] = a; }
                }
                __syncthreads();
            }
            v = skeys[tid];
            #pragma unroll
            for (int j = 16; j >= 1; j >>= 1) {
                unsigned long long o = __shfl_xor_sync(0xffffffffu, v, j);
                bool keepmin = (((tid & kk) == 0) == ((tid & j) == 0));
                v = keepmin ? (v < o ? v : o) : (v > o ? v : o);
            }
            skeys[tid] = v;
            __syncthreads();
        }
        if (tid < M) d_keys[tid] = skeys[tid];
    } else {
        // generic fallback up to n=8192 (M > 1024: ~never for this dist)
        int n = 1;
        while (n < M) n <<= 1;
        for (int k = tid; k < n; k += NT)
            skeys[k] = (k < M) ? d_keys[k] : ~0ull;
        __syncthreads();
        for (int kk = 2; kk <= n; kk <<= 1) {
            for (int j = kk >> 1; j > 0; j >>= 1) {
                for (int i = tid; i < n; i += NT) {
                    int ixj = i ^ j;
                    if (ixj > i) {
                        unsigned long long a = skeys[i];
                        unsigned long long c = skeys[ixj];
                        bool asc = ((i & kk) == 0);
                        if ((a > c) == asc) { skeys[i] = c; skeys[ixj] = a; }
                    }
                }
                __syncthreads();
            }
        }
        for (int k = tid; k < M; k += NT) d_keys[k] = skeys[k];
    }
}

// ---------------- K3: gather + write rows + NMS ----------------
// smem: float4 bx[6400] = 102400 | int ndlist[6400] = 25600 |
//       u8 ndflag[6400] | u8 kb[6400]
#define BX_OFF     0
#define NDLIST_OFF 102400
#define NDFLAG_OFF 128000
#define KB_OFF     134400
#define SMEM_G     140800

__global__ void __launch_bounds__(NT, 1)
bb_gather_nms(const float* __restrict__ x, float* __restrict__ out) {
    extern __shared__ unsigned char smem[];
    float4*        bx     = (float4*)(smem + BX_OFF);
    int*           ndlist = (int*)(smem + NDLIST_OFF);
    unsigned char* ndflag = smem + NDFLAG_OFF;
    unsigned char* kb     = smem + KB_OFF;
    const int tid  = threadIdx.x;
    const int lane = tid & 31;
    const int M = d_cnt;

    if (M > 0) {
        // gather channels by sorted index; f0 recovered from key bits.
        // b5 = (f0, f1, f0+f2, f1+f3, f4); box = (f1, f0+f2, f1+f3, f4)
        for (int r = tid; r < M; r += NT) {
            unsigned long long key = d_keys[r];
            unsigned i = (unsigned)key;
            float f0 = __uint_as_float(~(unsigned)(key >> 32));
            float f1 = x[NPIX + i];
            float f2 = x[2 * NPIX + i];
            float f3 = x[3 * NPIX + i];
            float f4 = x[4 * NPIX + i];
            float c2 = f0 + f2;
            float c3 = f1 + f3;
            out[r * 5 + 0] = f0;
            out[r * 5 + 1] = f1;
            out[r * 5 + 2] = c2;
            out[r * 5 + 3] = c3;
            out[r * 5 + 4] = f4;
            bx[r] = make_float4(f1, c2, c3, f4);
            ndflag[r] = ((c3 - f1) > 0.f && (f4 - c2) > 0.f) ? 1 : 0;
        }
        __syncthreads();

        // warp 0: greedy NMS over non-degenerate boxes only.
        // degenerate (w<=0 or h<=0) boxes have IoU 0 with everything:
        // never suppressed, never suppress -> rows stay as written.
        if (tid < 32) {
            int g = 0;
            for (int base = 0; base < M; base += 32) {
                int r = base + lane;
                bool f = (r < M) && (ndflag[r] != 0);
                unsigned bal = __ballot_sync(0xffffffffu, f);
                if (f) ndlist[g + __popc(bal & ((1u << lane) - 1u))] = r;
                g += __popc(bal);
            }
            for (int i2 = 0; i2 < g; i2++) {
                int ri = ndlist[i2];
                float4 a = bx[ri];
                float aarea = fmaxf(a.z - a.x, 0.f) * fmaxf(a.w - a.y, 0.f);
                bool sup = false;
                for (int j = lane; j < i2; j += 32) {
                    if (kb[j]) {
                        float4 b = bx[ndlist[j]];
                        float barea = fmaxf(b.z - b.x, 0.f) *
                                      fmaxf(b.w - b.y, 0.f);
                        float iw = fminf(a.z, b.z) - fmaxf(a.x, b.x);
                        float ih = fminf(a.w, b.w) - fmaxf(a.y, b.y);
                        float inter = fmaxf(iw, 0.f) * fmaxf(ih, 0.f);
                        float uni = aarea + barea - inter;
                        if (inter / fmaxf(uni, 1e-9f) > 0.5f) sup = true;
                    }
                }
                sup = __any_sync(0xffffffffu, sup);
                if (lane == 0) {
                    kb[i2] = sup ? 0 : 1;
                    if (sup) {   // suppressed row -> zeros
                        out[ri * 5 + 0] = 0.f;
                        out[ri * 5 + 1] = 0.f;
                        out[ri * 5 + 2] = 0.f;
                        out[ri * 5 + 3] = 0.f;
                        out[ri * 5 + 4] = 0.f;
                    }
                }
                __syncwarp();
            }
        }
    }
    __syncthreads();
    if (tid == 0) d_cnt = 0;   // reset for next replay
}

extern "C" void kernel_launch(void* const* d_in, const int* in_sizes, int n_in,
                              void* d_out, int out_size) {
    const float* x = (const float*)d_in[0];
    float* out = (float*)d_out;
    cudaFuncSetAttribute(bb_sort,
                         cudaFuncAttributeMaxDynamicSharedMemorySize,
                         SMEM_SORT);
    cudaFuncSetAttribute(bb_gather_nms,
                         cudaFuncAttributeMaxDynamicSharedMemorySize,
                         SMEM_G);
    bb_compact<<<64, 256>>>(x, out);
    bb_sort<<<1, NT, SMEM_SORT>>>();
    bb_gather_nms<<<1, NT, SMEM_G>>>(x, out);
}